// round 12
// baseline (speedup 1.0000x reference)
#include <cuda_runtime.h>
#include <cuda_fp16.h>
#include <math.h>
#include <stdint.h>

#define D_MODEL 4096
#define N_EXP   64
#define TOPK    8
#define M_CTA   128
#define TPB     256
#define KC      32
#define NCH     (D_MODEL / KC)     // 128
#define NKS     (D_MODEL / 16)     // 256 k16-steps
#define NSTG    4                  // W smem stages

#define WTB     8192               // per-chunk W bytes (2 ksteps x 64e x 4tg x 16B)
#define LBYTES  (M_CTA * 66 * 4)   // 33792 epilogue logits
#define SMEMB   (LBYTES > NSTG * WTB ? LBYTES : NSTG * WTB)
#define LROW    66
#define SCALE_LO 2048.0f
#define INV_SCALE_LO (1.0f / 2048.0f)

// Pre-packed W: entry (S, e, tg) = {bh_pair0, bh_pair1, bl_pair0, bl_pair1}
__device__ uint4 Wp_g[NKS * N_EXP * 4];

__global__ void pack_W(const float* __restrict__ W)
{
    int i = blockIdx.x * 256 + threadIdx.x;     // i = S*256 + e*4 + tg
    if (i >= NKS * N_EXP * 4) return;
    int S = i >> 8, r = i & 255;
    int e = r >> 2, tg = r & 3;
    int k0 = S * 16 + 2 * tg;
    const float* wr = W + (size_t)e * D_MODEL;

    float w00 = wr[k0],     w01 = wr[k0 + 1];
    float w10 = wr[k0 + 8], w11 = wr[k0 + 9];

    __half h00 = __float2half_rn(w00), h01 = __float2half_rn(w01);
    __half h10 = __float2half_rn(w10), h11 = __float2half_rn(w11);
    __half l00 = __float2half_rn((w00 - __half2float(h00)) * SCALE_LO);
    __half l01 = __float2half_rn((w01 - __half2float(h01)) * SCALE_LO);
    __half l10 = __float2half_rn((w10 - __half2float(h10)) * SCALE_LO);
    __half l11 = __float2half_rn((w11 - __half2float(h11)) * SCALE_LO);

    __half2 hp0 = __halves2half2(h00, h01);
    __half2 hp1 = __halves2half2(h10, h11);
    __half2 lp0 = __halves2half2(l00, l01);
    __half2 lp1 = __halves2half2(l10, l11);

    uint4 v;
    v.x = *(uint32_t*)&hp0; v.y = *(uint32_t*)&hp1;
    v.z = *(uint32_t*)&lp0; v.w = *(uint32_t*)&lp1;
    Wp_g[i] = v;
}

__device__ __forceinline__ void cpa16(uint32_t dst, const void* src) {
    asm volatile("cp.async.ca.shared.global [%0], [%1], 16;\n" :: "r"(dst), "l"(src));
}
__device__ __forceinline__ void cpa_commit() { asm volatile("cp.async.commit_group;\n"); }
template <int N> __device__ __forceinline__ void cpa_wait() {
    asm volatile("cp.async.wait_group %0;\n" :: "n"(N));
}

__device__ __forceinline__ void mma_f16(float* d, const uint32_t* a,
                                        uint32_t b0, uint32_t b1)
{
    asm volatile(
        "mma.sync.aligned.m16n8k16.row.col.f32.f16.f16.f32 "
        "{%0,%1,%2,%3}, {%4,%5,%6,%7}, {%8,%9}, {%0,%1,%2,%3};"
        : "+f"(d[0]), "+f"(d[1]), "+f"(d[2]), "+f"(d[3])
        : "r"(a[0]), "r"(a[1]), "r"(a[2]), "r"(a[3]), "r"(b0), "r"(b1));
}

__device__ __forceinline__ void split2(float2 f, uint32_t& h2, uint32_t& l2)
{
    __half2 h = __float22half2_rn(f);
    float2 hf = __half22float2(h);
    float2 l = make_float2((f.x - hf.x) * SCALE_LO, (f.y - hf.y) * SCALE_LO);
    __half2 lo = __float22half2_rn(l);
    h2 = *(uint32_t*)&h;
    l2 = *(uint32_t*)&lo;
}

// issue W chunk T into stage (cp.async), 512 x 16B chunks over 256 threads
__device__ __forceinline__ void load_W(uint32_t sb, int T, int t)
{
    const char* wsrc = (const char*)Wp_g + (size_t)T * WTB;
    uint32_t dst = sb + (T & (NSTG - 1)) * WTB;
#pragma unroll
    for (int i = 0; i < 2; i++) {
        int c = t + i * TPB;
        cpa16(dst + c * 16, wsrc + c * 16);
    }
}

// load one chunk's A raw data (8 float2 per thread) directly from global
__device__ __forceinline__ void load_A(float2* v, const float* xr0,
                                       const float* xr1, int d0, int tg)
{
    v[0] = *(const float2*)(xr0 + d0 + 2 * tg);
    v[1] = *(const float2*)(xr1 + d0 + 2 * tg);
    v[2] = *(const float2*)(xr0 + d0 + 2 * tg + 8);
    v[3] = *(const float2*)(xr1 + d0 + 2 * tg + 8);
    v[4] = *(const float2*)(xr0 + d0 + 16 + 2 * tg);
    v[5] = *(const float2*)(xr1 + d0 + 16 + 2 * tg);
    v[6] = *(const float2*)(xr0 + d0 + 16 + 2 * tg + 8);
    v[7] = *(const float2*)(xr1 + d0 + 16 + 2 * tg + 8);
}

__global__ void __launch_bounds__(TPB, 1)
router_kernel(const float* __restrict__ x, float* __restrict__ out,
              int n_tokens, long long out_size)
{
    extern __shared__ char smem[];
    const uint32_t sb = (uint32_t)__cvta_generic_to_shared(smem);

    const int t    = threadIdx.x;
    const int lane = t & 31;
    const int wid  = t >> 5;
    const int g    = lane >> 2;
    const int tg   = lane & 3;
    const int m0   = wid * 16;
    const int blk_tok = blockIdx.x * M_CTA;

    // warp-private x row pointers (clamped)
    int r0 = blk_tok + m0 + g;     if (r0 >= n_tokens) r0 = n_tokens - 1;
    int r1 = blk_tok + m0 + g + 8; if (r1 >= n_tokens) r1 = n_tokens - 1;
    const float* xr0 = x + (size_t)r0 * D_MODEL;
    const float* xr1 = x + (size_t)r1 * D_MODEL;

    float accH[8][4], masterH[8][4], accS[8][4];
#pragma unroll
    for (int n = 0; n < 8; n++)
#pragma unroll
        for (int j = 0; j < 4; j++) {
            accH[n][j] = 0.f; masterH[n][j] = 0.f; accS[n][j] = 0.f;
        }

    // prologue: W stages 0..2, A chunk 0
    load_W(sb, 0, t); cpa_commit();
    load_W(sb, 1, t); cpa_commit();
    load_W(sb, 2, t); cpa_commit();

    float2 xv[2][8];
    load_A(xv[0], xr0, xr1, 0, tg);

    for (int T = 0; T < NCH; T++) {
        const int cur = T & 1;
        cpa_wait<2>();
        __syncthreads();

        if (T + 3 < NCH) { load_W(sb, T + 3, t); cpa_commit(); }

        // prefetch next chunk's A into the alternate register buffer
        if (T + 1 < NCH)
            load_A(xv[cur ^ 1], xr0, xr1, (T + 1) * KC, tg);

        const char* ws = smem + (T & (NSTG - 1)) * WTB;
        const float2* av = xv[cur];

#pragma unroll
        for (int ks = 0; ks < 2; ks++) {
            uint32_t ah[4], al[4];
            split2(av[ks * 4 + 0], ah[0], al[0]);
            split2(av[ks * 4 + 1], ah[1], al[1]);
            split2(av[ks * 4 + 2], ah[2], al[2]);
            split2(av[ks * 4 + 3], ah[3], al[3]);

            const uint4* wrow = (const uint4*)(ws + ks * 4096) + tg;
#pragma unroll
            for (int n = 0; n < 8; n++) {
                uint4 wb = wrow[(n * 8 + g) * 4];
                mma_f16(accH[n], ah, wb.x, wb.y);   // hh
                mma_f16(accS[n], ah, wb.z, wb.w);   // h * lo(scaled)
                mma_f16(accS[n], al, wb.x, wb.y);   // lo(scaled) * h
            }
        }

        if ((T & 7) == 7) {
#pragma unroll
            for (int n = 0; n < 8; n++)
#pragma unroll
                for (int j = 0; j < 4; j++) {
                    masterH[n][j] += accH[n][j];
                    accH[n][j] = 0.f;
                }
        }
    }

    __syncthreads();   // all W-stage reads done before smem reuse as logits

    // ---- epilogue: combine (descale small terms), scatter logits ----
    float* L = (float*)smem;
#pragma unroll
    for (int n = 0; n < 8; n++) {
        int col = n * 8 + 2 * tg;
        float c0 = masterH[n][0] + accS[n][0] * INV_SCALE_LO;
        float c1 = masterH[n][1] + accS[n][1] * INV_SCALE_LO;
        float c2 = masterH[n][2] + accS[n][2] * INV_SCALE_LO;
        float c3 = masterH[n][3] + accS[n][3] * INV_SCALE_LO;
        *(float2*)&L[(m0 + g) * LROW + col]     = make_float2(c0, c1);
        *(float2*)&L[(m0 + g + 8) * LROW + col] = make_float2(c2, c3);
    }
    __syncthreads();

    if (t < M_CTA) {
        const int n = blk_tok + t;
        if (n < n_tokens) {
            float p[N_EXP];
            const float* Lr = L + t * LROW;
#pragma unroll
            for (int e = 0; e < N_EXP; e++) p[e] = Lr[e];

            float m = p[0];
#pragma unroll
            for (int e = 1; e < N_EXP; e++) m = fmaxf(m, p[e]);
            float ssum = 0.f;
#pragma unroll
            for (int e = 0; e < N_EXP; e++) { p[e] = expf(p[e] - m); ssum += p[e]; }
            float inv = 1.0f / ssum;
#pragma unroll
            for (int e = 0; e < N_EXP; e++) p[e] *= inv;

            const long long NK   = (long long)n_tokens * TOPK;
            const long long full = 2 * NK + (long long)n_tokens * N_EXP;

            if (out_size >= full) {
                float* pout = out + 2 * NK + (size_t)n * N_EXP;
#pragma unroll
                for (int e = 0; e < N_EXP; e++) pout[e] = p[e];
            }

            float tv[TOPK];
            int   ti[TOPK];
#pragma unroll
            for (int k = 0; k < TOPK; k++) { tv[k] = -1.0f; ti[k] = 0; }
#pragma unroll
            for (int e = 0; e < N_EXP; e++) {
                float v = p[e];
                if (v > tv[TOPK - 1]) {
                    tv[TOPK - 1] = v;
                    ti[TOPK - 1] = e;
#pragma unroll
                    for (int j = TOPK - 1; j > 0; j--) {
                        if (tv[j] > tv[j - 1]) {
                            float tf = tv[j]; tv[j] = tv[j - 1]; tv[j - 1] = tf;
                            int   tn = ti[j]; ti[j] = ti[j - 1]; ti[j - 1] = tn;
                        }
                    }
                }
            }
            float ws2 = 0.f;
#pragma unroll
            for (int k = 0; k < TOPK; k++) ws2 += tv[k];
            float winv = 1.0f / (ws2 + 1e-9f);

            if (out_size >= 2 * NK) {
#pragma unroll
                for (int k = 0; k < TOPK; k++) {
                    out[(size_t)n * TOPK + k]      = (float)ti[k];
                    out[NK + (size_t)n * TOPK + k] = tv[k] * winv;
                }
            } else if (out_size >= NK) {
#pragma unroll
                for (int k = 0; k < TOPK; k++)
                    out[(size_t)n * TOPK + k] = (float)ti[k];
            }
        }
    }
}

extern "C" void kernel_launch(void* const* d_in, const int* in_sizes, int n_in,
                              void* d_out, int out_size)
{
    const float* x = (const float*)d_in[0];
    const float* W = (const float*)d_in[1];
    int n_tokens = in_sizes[0] / D_MODEL;            // 16384

    pack_W<<<(NKS * N_EXP * 4 + 255) / 256, 256>>>(W);

    cudaFuncSetAttribute(router_kernel,
                         cudaFuncAttributeMaxDynamicSharedMemorySize, SMEMB);
    int grid = (n_tokens + M_CTA - 1) / M_CTA;       // 128
    router_kernel<<<grid, TPB, SMEMB>>>(x, (float*)d_out, n_tokens,
                                        (long long)out_size);
}

// round 13
// speedup vs baseline: 2.3587x; 2.3587x over previous
#include <cuda_runtime.h>
#include <cuda_fp16.h>
#include <math.h>
#include <stdint.h>

#define D_MODEL 4096
#define N_EXP   64
#define TOPK    8
#define M_CTA   128
#define TPB     256
#define KC      32
#define NCH     (D_MODEL / KC)     // 128
#define NKS     (D_MODEL / 16)     // 256 k16-steps
#define NSTG    4

#define XROW    40                        // padded floats per x smem row
#define XTB     (M_CTA * XROW * 4)        // 20480
#define WTB     (2 * N_EXP * 4 * 16)      // 8192
#define STAGE   (XTB + WTB)               // 28672
#define SMEMB   (NSTG * STAGE)            // 114688
#define LROW    66
#define SCALE_LO 2048.0f
#define INV_SCALE_LO (1.0f / 2048.0f)

// Pre-packed W: entry (S, e, tg) = {bh_pair0, bh_pair1, bl_pair0, bl_pair1}
__device__ uint4 Wp_g[NKS * N_EXP * 4];

__global__ void pack_W(const float* __restrict__ W)
{
    int i = blockIdx.x * 256 + threadIdx.x;     // i = S*256 + e*4 + tg
    if (i >= NKS * N_EXP * 4) return;
    int S = i >> 8, r = i & 255;
    int e = r >> 2, tg = r & 3;
    int k0 = S * 16 + 2 * tg;
    const float* wr = W + (size_t)e * D_MODEL;

    float w00 = wr[k0],     w01 = wr[k0 + 1];
    float w10 = wr[k0 + 8], w11 = wr[k0 + 9];

    __half h00 = __float2half_rn(w00), h01 = __float2half_rn(w01);
    __half h10 = __float2half_rn(w10), h11 = __float2half_rn(w11);
    __half l00 = __float2half_rn((w00 - __half2float(h00)) * SCALE_LO);
    __half l01 = __float2half_rn((w01 - __half2float(h01)) * SCALE_LO);
    __half l10 = __float2half_rn((w10 - __half2float(h10)) * SCALE_LO);
    __half l11 = __float2half_rn((w11 - __half2float(h11)) * SCALE_LO);

    __half2 hp0 = __halves2half2(h00, h01);
    __half2 hp1 = __halves2half2(h10, h11);
    __half2 lp0 = __halves2half2(l00, l01);
    __half2 lp1 = __halves2half2(l10, l11);

    uint4 v;
    v.x = *(uint32_t*)&hp0; v.y = *(uint32_t*)&hp1;
    v.z = *(uint32_t*)&lp0; v.w = *(uint32_t*)&lp1;
    Wp_g[i] = v;
}

__device__ __forceinline__ void cpa16(uint32_t dst, const void* src) {
    asm volatile("cp.async.ca.shared.global [%0], [%1], 16;\n" :: "r"(dst), "l"(src));
}
__device__ __forceinline__ void cpa_commit() { asm volatile("cp.async.commit_group;\n"); }
template <int N> __device__ __forceinline__ void cpa_wait() {
    asm volatile("cp.async.wait_group %0;\n" :: "n"(N));
}

__device__ __forceinline__ void mma_f16(float* d, const uint32_t* a,
                                        uint32_t b0, uint32_t b1)
{
    asm volatile(
        "mma.sync.aligned.m16n8k16.row.col.f32.f16.f16.f32 "
        "{%0,%1,%2,%3}, {%4,%5,%6,%7}, {%8,%9}, {%0,%1,%2,%3};"
        : "+f"(d[0]), "+f"(d[1]), "+f"(d[2]), "+f"(d[3])
        : "r"(a[0]), "r"(a[1]), "r"(a[2]), "r"(a[3]), "r"(b0), "r"(b1));
}

__device__ __forceinline__ void split2(float2 f, uint32_t& h2, uint32_t& l2)
{
    __half2 h = __float22half2_rn(f);
    float2 hf = __half22float2(h);
    float2 l = make_float2((f.x - hf.x) * SCALE_LO, (f.y - hf.y) * SCALE_LO);
    __half2 lo = __float22half2_rn(l);
    h2 = *(uint32_t*)&h;
    l2 = *(uint32_t*)&lo;
}

__device__ __forceinline__ void load_stage(uint32_t sb, const float* __restrict__ x,
                                           int blk_tok, int T, int n_tokens, int t)
{
    const uint32_t sbase = (uint32_t)((T & (NSTG - 1)) * STAGE);
    const int d0 = T * KC;
    // x tile: 128 rows x 8 chunks of 16B (rows padded to 160B): 1024 chunks
#pragma unroll
    for (int i = 0; i < 4; i++) {
        int c = t + i * TPB;
        int row = c >> 3, seg = c & 7;
        int tok = blk_tok + row; if (tok >= n_tokens) tok = n_tokens - 1;
        cpa16(sb + sbase + row * (XROW * 4) + seg * 16,
              x + (size_t)tok * D_MODEL + d0 + seg * 4);
    }
    // W tile: contiguous 8192B from Wp_g (chunk T owns ksteps 2T, 2T+1)
    const char* wsrc = (const char*)Wp_g + (size_t)T * WTB;
#pragma unroll
    for (int i = 0; i < 2; i++) {
        int c = t + i * TPB;
        cpa16(sb + sbase + XTB + c * 16, wsrc + c * 16);
    }
}

__global__ void __launch_bounds__(TPB, 1)
router_kernel(const float* __restrict__ x, float* __restrict__ out,
              int n_tokens, long long out_size)
{
    extern __shared__ char smem[];
    const uint32_t sb = (uint32_t)__cvta_generic_to_shared(smem);

    const int t    = threadIdx.x;
    const int lane = t & 31;
    const int wid  = t >> 5;
    const int g    = lane >> 2;
    const int tg   = lane & 3;
    const int m0   = wid * 16;
    const int blk_tok = blockIdx.x * M_CTA;

    float accH[8][4], masterH[8][4], accS[8][4];
#pragma unroll
    for (int n = 0; n < 8; n++)
#pragma unroll
        for (int j = 0; j < 4; j++) {
            accH[n][j] = 0.f; masterH[n][j] = 0.f; accS[n][j] = 0.f;
        }

    // prologue: chunks 0,1,2 in flight
    load_stage(sb, x, blk_tok, 0, n_tokens, t); cpa_commit();
    load_stage(sb, x, blk_tok, 1, n_tokens, t); cpa_commit();
    load_stage(sb, x, blk_tok, 2, n_tokens, t); cpa_commit();

    for (int T = 0; T < NCH; T++) {
        // chunk T must be resident (up to 2 younger groups may stay in flight)
        if (T + 2 < NCH)      cpa_wait<2>();
        else if (T + 1 < NCH) cpa_wait<1>();
        else                  cpa_wait<0>();
        __syncthreads();   // single barrier per chunk

        // overwrite stage (T+3)&3 == stage of chunk T-1 (reads done pre-sync)
        if (T + 3 < NCH) {
            load_stage(sb, x, blk_tok, T + 3, n_tokens, t);
            cpa_commit();
        }

        const float* xs = (const float*)(smem + (T & (NSTG - 1)) * STAGE);
        const char*  ws = smem + (T & (NSTG - 1)) * STAGE + XTB;

        const float* xr0 = xs + (m0 + g) * XROW;
        const float* xr1 = xs + (m0 + g + 8) * XROW;

#pragma unroll
        for (int ks = 0; ks < 2; ks++) {
            const int k0 = ks * 16;

            float2 f00 = *(const float2*)(xr0 + k0 + 2 * tg);
            float2 f10 = *(const float2*)(xr1 + k0 + 2 * tg);
            float2 f01 = *(const float2*)(xr0 + k0 + 2 * tg + 8);
            float2 f11 = *(const float2*)(xr1 + k0 + 2 * tg + 8);
            uint32_t ah[4], al[4];
            split2(f00, ah[0], al[0]);
            split2(f10, ah[1], al[1]);
            split2(f01, ah[2], al[2]);
            split2(f11, ah[3], al[3]);

            const uint4* wrow = (const uint4*)(ws + ks * 4096) + tg;
#pragma unroll
            for (int n = 0; n < 8; n++) {
                uint4 wb = wrow[(n * 8 + g) * 4];
                mma_f16(accH[n], ah, wb.x, wb.y);   // hh
                mma_f16(accS[n], ah, wb.z, wb.w);   // h * lo(scaled)
                mma_f16(accS[n], al, wb.x, wb.y);   // lo(scaled) * h
            }
        }

        // flush hh chunk accumulator every 8 chunks (two-level accumulation)
        if ((T & 7) == 7) {
#pragma unroll
            for (int n = 0; n < 8; n++)
#pragma unroll
                for (int j = 0; j < 4; j++) {
                    masterH[n][j] += accH[n][j];
                    accH[n][j] = 0.f;
                }
        }
    }

    __syncthreads();   // all stage reads complete before smem reuse as logits

    // ---- epilogue: combine (descale small terms), scatter logits ----
    float* L = (float*)smem;
#pragma unroll
    for (int n = 0; n < 8; n++) {
        int col = n * 8 + 2 * tg;
        float c0 = masterH[n][0] + accS[n][0] * INV_SCALE_LO;
        float c1 = masterH[n][1] + accS[n][1] * INV_SCALE_LO;
        float c2 = masterH[n][2] + accS[n][2] * INV_SCALE_LO;
        float c3 = masterH[n][3] + accS[n][3] * INV_SCALE_LO;
        *(float2*)&L[(m0 + g) * LROW + col]     = make_float2(c0, c1);
        *(float2*)&L[(m0 + g + 8) * LROW + col] = make_float2(c2, c3);
    }
    __syncthreads();

    if (t < M_CTA) {
        const int n = blk_tok + t;
        if (n < n_tokens) {
            float p[N_EXP];
            const float* Lr = L + t * LROW;
#pragma unroll
            for (int e = 0; e < N_EXP; e++) p[e] = Lr[e];

            float m = p[0];
#pragma unroll
            for (int e = 1; e < N_EXP; e++) m = fmaxf(m, p[e]);
            float ssum = 0.f;
#pragma unroll
            for (int e = 0; e < N_EXP; e++) { p[e] = expf(p[e] - m); ssum += p[e]; }
            float inv = 1.0f / ssum;
#pragma unroll
            for (int e = 0; e < N_EXP; e++) p[e] *= inv;

            const long long NK   = (long long)n_tokens * TOPK;
            const long long full = 2 * NK + (long long)n_tokens * N_EXP;

            if (out_size >= full) {
                float* pout = out + 2 * NK + (size_t)n * N_EXP;
#pragma unroll
                for (int e = 0; e < N_EXP; e++) pout[e] = p[e];
            }

            float tv[TOPK];
            int   ti[TOPK];
#pragma unroll
            for (int k = 0; k < TOPK; k++) { tv[k] = -1.0f; ti[k] = 0; }
#pragma unroll
            for (int e = 0; e < N_EXP; e++) {
                float v = p[e];
                if (v > tv[TOPK - 1]) {
                    tv[TOPK - 1] = v;
                    ti[TOPK - 1] = e;
#pragma unroll
                    for (int j = TOPK - 1; j > 0; j--) {
                        if (tv[j] > tv[j - 1]) {
                            float tf = tv[j]; tv[j] = tv[j - 1]; tv[j - 1] = tf;
                            int   tn = ti[j]; ti[j] = ti[j - 1]; ti[j - 1] = tn;
                        }
                    }
                }
            }
            float ws2 = 0.f;
#pragma unroll
            for (int k = 0; k < TOPK; k++) ws2 += tv[k];
            float winv = 1.0f / (ws2 + 1e-9f);

            if (out_size >= 2 * NK) {
#pragma unroll
                for (int k = 0; k < TOPK; k++) {
                    out[(size_t)n * TOPK + k]      = (float)ti[k];
                    out[NK + (size_t)n * TOPK + k] = tv[k] * winv;
                }
            } else if (out_size >= NK) {
#pragma unroll
                for (int k = 0; k < TOPK; k++)
                    out[(size_t)n * TOPK + k] = (float)ti[k];
            }
        }
    }
}

extern "C" void kernel_launch(void* const* d_in, const int* in_sizes, int n_in,
                              void* d_out, int out_size)
{
    const float* x = (const float*)d_in[0];
    const float* W = (const float*)d_in[1];
    int n_tokens = in_sizes[0] / D_MODEL;            // 16384

    pack_W<<<(NKS * N_EXP * 4 + 255) / 256, 256>>>(W);

    cudaFuncSetAttribute(router_kernel,
                         cudaFuncAttributeMaxDynamicSharedMemorySize, SMEMB);
    int grid = (n_tokens + M_CTA - 1) / M_CTA;       // 128
    router_kernel<<<grid, TPB, SMEMB>>>(x, (float*)d_out, n_tokens,
                                        (long long)out_size);
}

// round 17
// speedup vs baseline: 2.4979x; 1.0590x over previous
#include <cuda_runtime.h>
#include <cuda_fp16.h>
#include <math.h>
#include <stdint.h>

#define D_MODEL 4096
#define N_EXP   64
#define TOPK    8
#define M_CTA   128
#define TPB     256
#define KC      64
#define NCH     (D_MODEL / KC)     // 64
#define NKS     (D_MODEL / 16)     // 256 k16-steps
#define NSTG    3

#define XROW    72                        // padded floats per x smem row (288B)
#define XTB     (M_CTA * XROW * 4)        // 36864
#define WTB     (4 * N_EXP * 4 * 16)      // 16384 (4 ksteps x 64e x 4tg x 16B)
#define STAGE   (XTB + WTB)               // 53248
#define SMEMB   (NSTG * STAGE)            // 159744
#define LROW    66
#define SCALE_LO 2048.0f
#define INV_SCALE_LO (1.0f / 2048.0f)

// Pre-packed W: entry (S, e, tg) = {bh_pair0, bh_pair1, bl_pair0, bl_pair1}
__device__ uint4 Wp_g[NKS * N_EXP * 4];

__global__ void pack_W(const float* __restrict__ W)
{
    int i = blockIdx.x * 256 + threadIdx.x;     // i = S*256 + e*4 + tg
    if (i >= NKS * N_EXP * 4) return;
    int S = i >> 8, r = i & 255;
    int e = r >> 2, tg = r & 3;
    int k0 = S * 16 + 2 * tg;
    const float* wr = W + (size_t)e * D_MODEL;

    float w00 = wr[k0],     w01 = wr[k0 + 1];
    float w10 = wr[k0 + 8], w11 = wr[k0 + 9];

    __half h00 = __float2half_rn(w00), h01 = __float2half_rn(w01);
    __half h10 = __float2half_rn(w10), h11 = __float2half_rn(w11);
    __half l00 = __float2half_rn((w00 - __half2float(h00)) * SCALE_LO);
    __half l01 = __float2half_rn((w01 - __half2float(h01)) * SCALE_LO);
    __half l10 = __float2half_rn((w10 - __half2float(h10)) * SCALE_LO);
    __half l11 = __float2half_rn((w11 - __half2float(h11)) * SCALE_LO);

    __half2 hp0 = __halves2half2(h00, h01);
    __half2 hp1 = __halves2half2(h10, h11);
    __half2 lp0 = __halves2half2(l00, l01);
    __half2 lp1 = __halves2half2(l10, l11);

    uint4 v;
    v.x = *(uint32_t*)&hp0; v.y = *(uint32_t*)&hp1;
    v.z = *(uint32_t*)&lp0; v.w = *(uint32_t*)&lp1;
    Wp_g[i] = v;
}

__device__ __forceinline__ void cpa16(uint32_t dst, const void* src) {
    asm volatile("cp.async.ca.shared.global [%0], [%1], 16;\n" :: "r"(dst), "l"(src));
}
__device__ __forceinline__ void cpa_commit() { asm volatile("cp.async.commit_group;\n"); }
template <int N> __device__ __forceinline__ void cpa_wait() {
    asm volatile("cp.async.wait_group %0;\n" :: "n"(N));
}

__device__ __forceinline__ void mma_f16(float* d, const uint32_t* a,
                                        uint32_t b0, uint32_t b1)
{
    asm volatile(
        "mma.sync.aligned.m16n8k16.row.col.f32.f16.f16.f32 "
        "{%0,%1,%2,%3}, {%4,%5,%6,%7}, {%8,%9}, {%0,%1,%2,%3};"
        : "+f"(d[0]), "+f"(d[1]), "+f"(d[2]), "+f"(d[3])
        : "r"(a[0]), "r"(a[1]), "r"(a[2]), "r"(a[3]), "r"(b0), "r"(b1));
}

__device__ __forceinline__ void split2(float2 f, uint32_t& h2, uint32_t& l2)
{
    __half2 h = __float22half2_rn(f);
    float2 hf = __half22float2(h);
    float2 l = make_float2((f.x - hf.x) * SCALE_LO, (f.y - hf.y) * SCALE_LO);
    __half2 lo = __float22half2_rn(l);
    h2 = *(uint32_t*)&h;
    l2 = *(uint32_t*)&lo;
}

__device__ __forceinline__ void load_stage(uint32_t sb, const float* __restrict__ x,
                                           int blk_tok, int T, int n_tokens, int t)
{
    const uint32_t sbase = (uint32_t)((T % NSTG) * STAGE);
    const int d0 = T * KC;
    // x tile: 128 rows x 16 segs of 16B (rows padded to 288B): 2048 chunks
#pragma unroll
    for (int i = 0; i < 8; i++) {
        int c = t + i * TPB;
        int row = c >> 4, seg = c & 15;
        int tok = blk_tok + row; if (tok >= n_tokens) tok = n_tokens - 1;
        cpa16(sb + sbase + row * (XROW * 4) + seg * 16,
              x + (size_t)tok * D_MODEL + d0 + seg * 4);
    }
    // W tile: contiguous 16384B from Wp_g (chunk T owns ksteps 4T..4T+3)
    const char* wsrc = (const char*)Wp_g + (size_t)T * WTB;
#pragma unroll
    for (int i = 0; i < 4; i++) {
        int c = t + i * TPB;
        cpa16(sb + sbase + XTB + c * 16, wsrc + c * 16);
    }
}

__global__ void __launch_bounds__(TPB, 1)
router_kernel(const float* __restrict__ x, float* __restrict__ out,
              int n_tokens, long long out_size)
{
    extern __shared__ char smem[];
    const uint32_t sb = (uint32_t)__cvta_generic_to_shared(smem);

    const int t    = threadIdx.x;
    const int lane = t & 31;
    const int wid  = t >> 5;
    const int g    = lane >> 2;
    const int tg   = lane & 3;
    const int m0   = wid * 16;
    const int blk_tok = blockIdx.x * M_CTA;

    float accH[8][4], masterH[8][4], accS[8][4];
#pragma unroll
    for (int n = 0; n < 8; n++)
#pragma unroll
        for (int j = 0; j < 4; j++) {
            accH[n][j] = 0.f; masterH[n][j] = 0.f; accS[n][j] = 0.f;
        }

    // prologue: chunks 0,1 in flight
    load_stage(sb, x, blk_tok, 0, n_tokens, t); cpa_commit();
    load_stage(sb, x, blk_tok, 1, n_tokens, t); cpa_commit();

    for (int T = 0; T < NCH; T++) {
        if (T + 1 < NCH) cpa_wait<1>(); else cpa_wait<0>();
        __syncthreads();   // single barrier per chunk

        // overwrite stage (T+2)%3 == stage of chunk T-1 (reads done pre-sync)
        if (T + 2 < NCH) {
            load_stage(sb, x, blk_tok, T + 2, n_tokens, t);
            cpa_commit();
        }

        const float* xs = (const float*)(smem + (T % NSTG) * STAGE);
        const char*  ws = smem + (T % NSTG) * STAGE + XTB;

        const float* xr0 = xs + (m0 + g) * XROW;
        const float* xr1 = xs + (m0 + g + 8) * XROW;

#pragma unroll
        for (int ks = 0; ks < 4; ks++) {
            const int k0 = ks * 16;

            float2 f00 = *(const float2*)(xr0 + k0 + 2 * tg);
            float2 f10 = *(const float2*)(xr1 + k0 + 2 * tg);
            float2 f01 = *(const float2*)(xr0 + k0 + 2 * tg + 8);
            float2 f11 = *(const float2*)(xr1 + k0 + 2 * tg + 8);
            uint32_t ah[4], al[4];
            split2(f00, ah[0], al[0]);
            split2(f10, ah[1], al[1]);
            split2(f01, ah[2], al[2]);
            split2(f11, ah[3], al[3]);

            const uint4* wrow = (const uint4*)(ws + ks * 4096) + tg;
#pragma unroll
            for (int n = 0; n < 8; n++) {
                uint4 wb = wrow[(n * 8 + g) * 4];
                mma_f16(accH[n], ah, wb.x, wb.y);   // hh
                mma_f16(accS[n], ah, wb.z, wb.w);   // h * lo(scaled)
                mma_f16(accS[n], al, wb.x, wb.y);   // lo(scaled) * h
            }
        }

        // flush hh every 4 chunks (= 256 d inner chain, same as before)
        if ((T & 3) == 3) {
#pragma unroll
            for (int n = 0; n < 8; n++)
#pragma unroll
                for (int j = 0; j < 4; j++) {
                    masterH[n][j] += accH[n][j];
                    accH[n][j] = 0.f;
                }
        }
    }

    __syncthreads();   // all stage reads complete before smem reuse as logits

    // ---- epilogue: combine (descale small terms), scatter logits ----
    float* L = (float*)smem;
#pragma unroll
    for (int n = 0; n < 8; n++) {
        int col = n * 8 + 2 * tg;
        float c0 = masterH[n][0] + accS[n][0] * INV_SCALE_LO;
        float c1 = masterH[n][1] + accS[n][1] * INV_SCALE_LO;
        float c2 = masterH[n][2] + accS[n][2] * INV_SCALE_LO;
        float c3 = masterH[n][3] + accS[n][3] * INV_SCALE_LO;
        *(float2*)&L[(m0 + g) * LROW + col]     = make_float2(c0, c1);
        *(float2*)&L[(m0 + g + 8) * LROW + col] = make_float2(c2, c3);
    }
    __syncthreads();

    if (t < M_CTA) {
        const int n = blk_tok + t;
        if (n < n_tokens) {
            float p[N_EXP];
            const float* Lr = L + t * LROW;
#pragma unroll
            for (int e = 0; e < N_EXP; e++) p[e] = Lr[e];

            float m = p[0];
#pragma unroll
            for (int e = 1; e < N_EXP; e++) m = fmaxf(m, p[e]);
            float ssum = 0.f;
#pragma unroll
            for (int e = 0; e < N_EXP; e++) { p[e] = expf(p[e] - m); ssum += p[e]; }
            float inv = 1.0f / ssum;
#pragma unroll
            for (int e = 0; e < N_EXP; e++) p[e] *= inv;

            const long long NK   = (long long)n_tokens * TOPK;
            const long long full = 2 * NK + (long long)n_tokens * N_EXP;

            if (out_size >= full) {
                float* pout = out + 2 * NK + (size_t)n * N_EXP;
#pragma unroll
                for (int e = 0; e < N_EXP; e++) pout[e] = p[e];
            }

            float tv[TOPK];
            int   ti[TOPK];
#pragma unroll
            for (int k = 0; k < TOPK; k++) { tv[k] = -1.0f; ti[k] = 0; }
#pragma unroll
            for (int e = 0; e < N_EXP; e++) {
                float v = p[e];
                if (v > tv[TOPK - 1]) {
                    tv[TOPK - 1] = v;
                    ti[TOPK - 1] = e;
#pragma unroll
                    for (int j = TOPK - 1; j > 0; j--) {
                        if (tv[j] > tv[j - 1]) {
                            float tf = tv[j]; tv[j] = tv[j - 1]; tv[j - 1] = tf;
                            int   tn = ti[j]; ti[j] = ti[j - 1]; ti[j - 1] = tn;
                        }
                    }
                }
            }
            float ws2 = 0.f;
#pragma unroll
            for (int k = 0; k < TOPK; k++) ws2 += tv[k];
            float winv = 1.0f / (ws2 + 1e-9f);

            if (out_size >= 2 * NK) {
#pragma unroll
                for (int k = 0; k < TOPK; k++) {
                    out[(size_t)n * TOPK + k]      = (float)ti[k];
                    out[NK + (size_t)n * TOPK + k] = tv[k] * winv;
                }
            } else if (out_size >= NK) {
#pragma unroll
                for (int k = 0; k < TOPK; k++)
                    out[(size_t)n * TOPK + k] = (float)ti[k];
            }
        }
    }
}

extern "C" void kernel_launch(void* const* d_in, const int* in_sizes, int n_in,
                              void* d_out, int out_size)
{
    const float* x = (const float*)d_in[0];
    const float* W = (const float*)d_in[1];
    int n_tokens = in_sizes[0] / D_MODEL;            // 16384

    pack_W<<<(NKS * N_EXP * 4 + 255) / 256, 256>>>(W);

    cudaFuncSetAttribute(router_kernel,
                         cudaFuncAttributeMaxDynamicSharedMemorySize, SMEMB);
    int grid = (n_tokens + M_CTA - 1) / M_CTA;       // 128
    router_kernel<<<grid, TPB, SMEMB>>>(x, (float*)d_out, n_tokens,
                                        (long long)out_size);
}